// round 9
// baseline (speedup 1.0000x reference)
#include <cuda_runtime.h>
#include <cstdint>

#define H 256
#define B 32
#define S 1024
#define NL 4
#define NE (H * B)            // 8192
#define G4 (4 * H)            // 1024
#define MROWS (S * B)         // 32768
#define LSTRIDE ((S + 1) * NE)  // per-layer h0/c0 slab stride

// -------- static scratch (allowed: __device__ globals) --------
__device__ float g_gates[(size_t)MROWS * G4];   // 128 MB: [t*B+b][4H]
__device__ float g_xbuf0[(size_t)MROWS * H];    // 32 MB:  [t*B+b][H]
__device__ float g_xbuf1[(size_t)MROWS * H];    // 32 MB

// -------- helpers --------
__device__ __forceinline__ void ffma2(unsigned long long& d,
                                      unsigned long long a,
                                      unsigned long long b) {
    asm("fma.rn.f32x2 %0, %1, %2, %0;" : "+l"(d) : "l"(a), "l"(b));
}
__device__ __forceinline__ unsigned long long dup2(float a) {
    unsigned long long r;
    asm("mov.b64 %0, {%1, %1};" : "=l"(r) : "f"(a));
    return r;
}
__device__ __forceinline__ float2 unpack2(unsigned long long v) {
    float2 f;
    asm("mov.b64 {%0, %1}, %2;" : "=f"(f.x), "=f"(f.y) : "l"(v));
    return f;
}
__device__ __forceinline__ uint32_t smem_u32(const void* p) {
    return (uint32_t)__cvta_generic_to_shared(p);
}
__device__ __forceinline__ uint32_t ctarank() {
    uint32_t r;
    asm("mov.u32 %0, %%cluster_ctarank;" : "=r"(r));
    return r;
}
__device__ __forceinline__ float sigm(float x) {
    return 1.0f / (1.0f + __expf(-x));
}

// ============================================================
// GEMM: C[M=32768, N=1024] = A[M,256] @ W^T + bias
// W is [1024, 256] row-major (row n = output gate n, cols = k).
// BM=128, BN=128, BK=16, 256 threads, 8x8 microtile w/ FFMA2.
// ============================================================
__global__ void __launch_bounds__(256)
lstm_gemm(const float* __restrict__ Aex, int asel,
          const float* __restrict__ Wl,
          const float* __restrict__ bl)
{
    const float* A = (asel == 0) ? Aex : (asel == 1 ? g_xbuf0 : g_xbuf1);
    float* Cout = g_gates;

    __shared__ __align__(16) float As[16][128];
    __shared__ __align__(16) float Bs[16][128];

    const int tid = threadIdx.x;
    const int n0 = blockIdx.x * 128;
    const int m0 = blockIdx.y * 128;
    const int tx = tid & 15, ty = tid >> 4;      // microtile coords
    const int lm = tid & 127, kq = tid >> 7;     // load roles

    unsigned long long acc[8][4];
#pragma unroll
    for (int i = 0; i < 8; i++)
#pragma unroll
        for (int j = 0; j < 4; j++) acc[i][j] = 0ull;

    const float* aptr = A  + (size_t)(m0 + lm) * 256 + kq * 8;
    const float* bptr = Wl + (size_t)(n0 + lm) * 256 + kq * 8;

    for (int kt = 0; kt < 256; kt += 16) {
        float4 a0 = *(const float4*)(aptr + kt);
        float4 a1 = *(const float4*)(aptr + kt + 4);
        float4 w0 = *(const float4*)(bptr + kt);
        float4 w1 = *(const float4*)(bptr + kt + 4);
        __syncthreads();   // protect previous iteration's frag reads
        As[kq * 8 + 0][lm] = a0.x; As[kq * 8 + 1][lm] = a0.y;
        As[kq * 8 + 2][lm] = a0.z; As[kq * 8 + 3][lm] = a0.w;
        As[kq * 8 + 4][lm] = a1.x; As[kq * 8 + 5][lm] = a1.y;
        As[kq * 8 + 6][lm] = a1.z; As[kq * 8 + 7][lm] = a1.w;
        Bs[kq * 8 + 0][lm] = w0.x; Bs[kq * 8 + 1][lm] = w0.y;
        Bs[kq * 8 + 2][lm] = w0.z; Bs[kq * 8 + 3][lm] = w0.w;
        Bs[kq * 8 + 4][lm] = w1.x; Bs[kq * 8 + 5][lm] = w1.y;
        Bs[kq * 8 + 6][lm] = w1.z; Bs[kq * 8 + 7][lm] = w1.w;
        __syncthreads();

#pragma unroll
        for (int k = 0; k < 16; k++) {
            unsigned long long b2[4];
#pragma unroll
            for (int j = 0; j < 4; j++)
                b2[j] = *(const unsigned long long*)&Bs[k][tx * 8 + 2 * j];
            float4 af0 = *(const float4*)&As[k][ty * 8];
            float4 af1 = *(const float4*)&As[k][ty * 8 + 4];
            float a[8] = {af0.x, af0.y, af0.z, af0.w, af1.x, af1.y, af1.z, af1.w};
#pragma unroll
            for (int i = 0; i < 8; i++) {
                unsigned long long a2 = dup2(a[i]);
#pragma unroll
                for (int j = 0; j < 4; j++) ffma2(acc[i][j], a2, b2[j]);
            }
        }
    }

    float bias_r[8];
#pragma unroll
    for (int j = 0; j < 8; j++) bias_r[j] = bl[n0 + tx * 8 + j];
#pragma unroll
    for (int i = 0; i < 8; i++) {
        float o[8];
#pragma unroll
        for (int j = 0; j < 4; j++) {
            float2 v = unpack2(acc[i][j]);
            o[2 * j + 0] = v.x + bias_r[2 * j + 0];
            o[2 * j + 1] = v.y + bias_r[2 * j + 1];
        }
        float* crow = Cout + (size_t)(m0 + ty * 8 + i) * G4 + n0 + tx * 8;
        *(float4*)(crow + 0) = make_float4(o[0], o[1], o[2], o[3]);
        *(float4*)(crow + 4) = make_float4(o[4], o[5], o[6], o[7]);
    }
}

// ============================================================
// Recurrence scan. Grid = 128 CTAs, cluster = 8 CTAs, 256 thr.
// Cluster c owns batches {2c, 2c+1}. CTA rank owns h-indices
// [rank*32, rank*32+32) for all 4 gates (128 R rows, registers).
// Thread: sub = tid&7 owns R/h columns {sub*2 + 16*k2 + e}.
// Per step: FFMA2 dot -> shfl(8) reduce -> epilogue (64 owner
// lanes) -> DSMEM multicast of new h -> barrier.cluster.
// ============================================================
__global__ void __launch_bounds__(256, 1) __cluster_dims__(8, 1, 1)
lstm_scan(const float* __restrict__ Rl,
          const float* __restrict__ h0,
          const float* __restrict__ c0,
          float* __restrict__ xex, int osel)
{
    float* xnext = (osel == 2) ? xex : (osel == 0 ? g_xbuf0 : g_xbuf1);
    const float* gates = g_gates;

    __shared__ __align__(16) float hs[2][2][H];        // parity, batch, hidden
    __shared__ __align__(16) float gxs[2][2][4][32];   // parity, batch, gate, jj
    __shared__ __align__(16) float hnew[2][32];        // staging for broadcast

    const int tid = threadIdx.x;
    const int rank = (int)ctarank();
    const int cid = blockIdx.x >> 3;
    const int b0 = cid * 2;
    const int sub = tid & 7;
    const int jj = tid >> 3;
    const int hidx = rank * 32 + jj;
    const bool owner = (sub == 0);

    // ---- register-resident R slice: 4 gates x 16 column pairs ----
    unsigned long long Rf[4][16];
#pragma unroll
    for (int g = 0; g < 4; g++) {
        const float* base = Rl + (size_t)(g * 256 + hidx) * 256;
#pragma unroll
        for (int k2 = 0; k2 < 16; k2++)
            Rf[g][k2] = *(const unsigned long long*)(base + sub * 2 + 16 * k2);
    }

    // ---- initial h (full 512 floats per CTA) and c (owner regs) ----
    for (int i = tid; i < 2 * H; i += 256) {
        int b = i >> 8, idx = i & 255;
        hs[0][b][idx] = h0[(size_t)(b0 + b) * H + idx];
    }
    float c0r = 0.f, c1r = 0.f;
    if (owner) {
        c0r = c0[(size_t)(b0 + 0) * H + hidx];
        c1r = c0[(size_t)(b0 + 1) * H + hidx];
    }

    // gate-x loader role for this thread (one value per step)
    const int gb = tid >> 7;
    const int grem = tid & 127;
    const int gg_ = grem >> 5;
    const int gj = grem & 31;
    const size_t gcol = (size_t)(gg_ * 256 + rank * 32 + gj);

    // preload gates_x for t = 0
    gxs[0][gb][gg_][gj] = gates[(size_t)(b0 + gb) * G4 + gcol];

    __syncthreads();
    asm volatile("barrier.cluster.arrive.aligned;" ::: "memory");
    asm volatile("barrier.cluster.wait.aligned;" ::: "memory");

    int p = 0;
    for (int t = 0; t < S; t++) {
        // prefetch next step's gates_x (hides DRAM latency under the dot)
        int t1 = (t + 1 < S) ? (t + 1) : (S - 1);
        float gnext = gates[(size_t)(t1 * B + b0 + gb) * G4 + gcol];

        // ---- dot product: acc[g][b] over owned columns ----
        unsigned long long acc[4][2] = {{0ull, 0ull}, {0ull, 0ull},
                                        {0ull, 0ull}, {0ull, 0ull}};
        const float* hp0 = &hs[p][0][sub * 2];
        const float* hp1 = &hs[p][1][sub * 2];
#pragma unroll
        for (int k2 = 0; k2 < 16; k2++) {
            unsigned long long h0v = *(const unsigned long long*)(hp0 + 16 * k2);
            unsigned long long h1v = *(const unsigned long long*)(hp1 + 16 * k2);
#pragma unroll
            for (int g = 0; g < 4; g++) {
                ffma2(acc[g][0], Rf[g][k2], h0v);
                ffma2(acc[g][1], Rf[g][k2], h1v);
            }
        }

        // ---- reduce over the 8-lane column group ----
        float red[4][2];
#pragma unroll
        for (int g = 0; g < 4; g++)
#pragma unroll
            for (int b = 0; b < 2; b++) {
                float2 v = unpack2(acc[g][b]);
                float s = v.x + v.y;
                s += __shfl_xor_sync(0xffffffffu, s, 1);
                s += __shfl_xor_sync(0xffffffffu, s, 2);
                s += __shfl_xor_sync(0xffffffffu, s, 4);
                red[g][b] = s;
            }

        __syncthreads();                       // gxs[t&1] ready, hnew free
        gxs[(t + 1) & 1][gb][gg_][gj] = gnext; // stage next step's gates_x

        if (owner) {
#pragma unroll
            for (int b = 0; b < 2; b++) {
                float gi = red[0][b] + gxs[t & 1][b][0][jj];
                float gf = red[1][b] + gxs[t & 1][b][1][jj];
                float gG = red[2][b] + gxs[t & 1][b][2][jj];
                float go = red[3][b] + gxs[t & 1][b][3][jj];
                float iv = sigm(gi);
                float fv = sigm(gf);
                float gv = tanhf(gG);
                float ov = sigm(go);
                float cold = b ? c1r : c0r;
                float cnew = fv * cold + iv * gv;
                if (b) c1r = cnew; else c0r = cnew;
                hnew[b][jj] = ov * tanhf(cnew);
            }
        }
        __syncthreads();                       // hnew ready

        // ---- DSMEM broadcast: 64 new h floats -> all 8 ranks ----
        {
            int r = tid >> 5;                  // target rank (one per warp)
            int idx2 = tid & 31;
            int b = idx2 >> 4, j2 = idx2 & 15;
            float2 v = ((const float2*)&hnew[b][0])[j2];
            uint32_t laddr = smem_u32(&hs[p ^ 1][b][rank * 32 + j2 * 2]);
            uint32_t raddr;
            asm volatile("mapa.shared::cluster.u32 %0, %1, %2;"
                         : "=r"(raddr) : "r"(laddr), "r"(r));
            asm volatile("st.shared::cluster.v2.f32 [%0], {%1, %2};"
                         :: "r"(raddr), "f"(v.x), "f"(v.y) : "memory");
        }
        asm volatile("barrier.cluster.arrive.aligned;" ::: "memory");

        // global write of this CTA's h slice (overlapped with barrier wait)
        if (tid < 16) {
            int b = tid >> 3, q = tid & 7;
            float4 v = ((const float4*)&hnew[b][0])[q];
            *(float4*)&xnext[(size_t)(t * B + b0 + b) * H + rank * 32 + q * 4] = v;
        }
        asm volatile("barrier.cluster.wait.aligned;" ::: "memory");
        p ^= 1;
    }
}

// ============================================================
// Host: 4 x (GEMM, SCAN), ping-pong x buffers, all on stream 0.
// ============================================================
extern "C" void kernel_launch(void* const* d_in, const int* in_sizes, int n_in,
                              void* d_out, int out_size)
{
    const float* h_data = (const float*)d_in[0];
    const float* x_data = (const float*)d_in[1];
    const float* c_data = (const float*)d_in[2];
    const float* W      = (const float*)d_in[3];
    const float* R      = (const float*)d_in[4];
    const float* bias   = (const float*)d_in[5];
    float* out = (float*)d_out;

    const dim3 ggrid(8, 256);     // N/128, M/128
    const size_t wstride = (size_t)G4 * H;   // per-layer W/R stride

    // layer 0: A = x_data, scan out -> xbuf0
    lstm_gemm<<<ggrid, 256>>>(x_data, 0, W + 0 * wstride, bias + 0 * G4);
    lstm_scan<<<128, 256>>>(R + 0 * wstride,
                            h_data + 0 * (size_t)LSTRIDE,
                            c_data + 0 * (size_t)LSTRIDE,
                            nullptr, 0);
    // layer 1: A = xbuf0, out -> xbuf1
    lstm_gemm<<<ggrid, 256>>>(nullptr, 1, W + 1 * wstride, bias + 1 * G4);
    lstm_scan<<<128, 256>>>(R + 1 * wstride,
                            h_data + 1 * (size_t)LSTRIDE,
                            c_data + 1 * (size_t)LSTRIDE,
                            nullptr, 1);
    // layer 2: A = xbuf1, out -> xbuf0
    lstm_gemm<<<ggrid, 256>>>(nullptr, 2, W + 2 * wstride, bias + 2 * G4);
    lstm_scan<<<128, 256>>>(R + 2 * wstride,
                            h_data + 2 * (size_t)LSTRIDE,
                            c_data + 2 * (size_t)LSTRIDE,
                            nullptr, 0);
    // layer 3: A = xbuf0, out -> d_out
    lstm_gemm<<<ggrid, 256>>>(nullptr, 1, W + 3 * wstride, bias + 3 * G4);
    lstm_scan<<<128, 256>>>(R + 3 * wstride,
                            h_data + 3 * (size_t)LSTRIDE,
                            c_data + 3 * (size_t)LSTRIDE,
                            out, 2);
}

// round 10
// speedup vs baseline: 1.6042x; 1.6042x over previous
#include <cuda_runtime.h>
#include <cstdint>

#define H 256
#define B 32
#define S 1024
#define NL 4
#define NE (H * B)              // 8192
#define G4 (4 * H)              // 1024
#define MROWS (S * B)           // 32768
#define LSTRIDE ((S + 1) * NE)  // per-layer h0/c0 slab stride

// -------- static scratch (allowed: __device__ globals) --------
__device__ float g_gates[(size_t)MROWS * G4];   // 128 MB: [t*B+b][4H]
__device__ float g_xbuf0[(size_t)MROWS * H];    // 32 MB:  [t*B+b][H]
__device__ float g_xbuf1[(size_t)MROWS * H];    // 32 MB

// -------- helpers --------
__device__ __forceinline__ void ffma2(unsigned long long& d,
                                      unsigned long long a,
                                      unsigned long long b) {
    asm("fma.rn.f32x2 %0, %1, %2, %0;" : "+l"(d) : "l"(a), "l"(b));
}
__device__ __forceinline__ unsigned long long dup2(float a) {
    unsigned long long r;
    asm("mov.b64 %0, {%1, %1};" : "=l"(r) : "f"(a));
    return r;
}
__device__ __forceinline__ float2 unpack2(unsigned long long v) {
    float2 f;
    asm("mov.b64 {%0, %1}, %2;" : "=f"(f.x), "=f"(f.y) : "l"(v));
    return f;
}
__device__ __forceinline__ uint32_t smem_u32(const void* p) {
    return (uint32_t)__cvta_generic_to_shared(p);
}
__device__ __forceinline__ uint32_t ctarank() {
    uint32_t r;
    asm("mov.u32 %0, %%cluster_ctarank;" : "=r"(r));
    return r;
}
__device__ __forceinline__ uint32_t mapa_rank(uint32_t laddr, int r) {
    uint32_t ra;
    asm("mapa.shared::cluster.u32 %0, %1, %2;" : "=r"(ra) : "r"(laddr), "r"(r));
    return ra;
}
// fast, branch-free activations (rel err ~1e-6; saturate correctly)
__device__ __forceinline__ float fsigm(float x) {
    return __fdividef(1.0f, 1.0f + __expf(-x));
}
__device__ __forceinline__ float ftanh(float x) {
    return __fdividef(2.0f, 1.0f + __expf(-2.0f * x)) - 1.0f;
}
__device__ __forceinline__ void mbar_init(uint32_t a, int cnt) {
    asm volatile("mbarrier.init.shared.b64 [%0], %1;" :: "r"(a), "r"(cnt) : "memory");
}
__device__ __forceinline__ void mbar_arrive_cluster(uint32_t a) {
    asm volatile("mbarrier.arrive.release.cluster.shared::cluster.b64 _, [%0];"
                 :: "r"(a) : "memory");
}
__device__ __forceinline__ void mbar_wait(uint32_t a, uint32_t parity) {
    uint32_t done;
    asm volatile(
        "{\n\t.reg .pred p;\n\t"
        "mbarrier.try_wait.parity.acquire.cluster.shared::cta.b64 p, [%1], %2;\n\t"
        "selp.b32 %0, 1, 0, p;\n\t}"
        : "=r"(done) : "r"(a), "r"(parity) : "memory");
    if (!done) {
        asm volatile(
            "{\n\t.reg .pred P1;\n\t"
            "W_%=:\n\t"
            "mbarrier.try_wait.parity.acquire.cluster.shared::cta.b64 P1, [%0], %1, 0x989680;\n\t"
            "@P1 bra.uni D_%=;\n\t"
            "bra.uni W_%=;\n\t"
            "D_%=:\n\t}"
            :: "r"(a), "r"(parity) : "memory");
    }
}

// ============================================================
// GEMM: C[M=32768, N=1024] = A[M,256] @ W^T + bias
// BM=128, BN=128, BK=16, 256 threads, 8x8 microtile, FFMA2.
// Coalesced loads + register prefetch of tile kt+1 under
// compute of tile kt. 2 CTAs resident per SM.
// ============================================================
__global__ void __launch_bounds__(256, 2)
lstm_gemm(const float* __restrict__ Aex, int asel,
          const float* __restrict__ Wl,
          const float* __restrict__ bl)
{
    const float* A = (asel == 0) ? Aex : (asel == 1 ? g_xbuf0 : g_xbuf1);
    float* Cout = g_gates;

    __shared__ __align__(16) float As[16][128];
    __shared__ __align__(16) float Bs[16][128];

    const int tid = threadIdx.x;
    const int n0 = blockIdx.x * 128;
    const int m0 = blockIdx.y * 128;
    const int tx = tid & 15, ty = tid >> 4;   // microtile coords

    // loader roles: thread handles rows lr and lr+64, k-chunk lk4 (float4)
    const int lr = tid >> 2;        // 0..63
    const int lk4 = tid & 3;        // 0..3

    unsigned long long acc[8][4];
#pragma unroll
    for (int i = 0; i < 8; i++)
#pragma unroll
        for (int j = 0; j < 4; j++) acc[i][j] = 0ull;

    const float* aP0 = A  + (size_t)(m0 + lr)      * 256 + lk4 * 4;
    const float* aP1 = A  + (size_t)(m0 + lr + 64) * 256 + lk4 * 4;
    const float* bP0 = Wl + (size_t)(n0 + lr)      * 256 + lk4 * 4;
    const float* bP1 = Wl + (size_t)(n0 + lr + 64) * 256 + lk4 * 4;

    float4 a0 = *(const float4*)(aP0);
    float4 a1 = *(const float4*)(aP1);
    float4 w0 = *(const float4*)(bP0);
    float4 w1 = *(const float4*)(bP1);

    for (int kt = 0; kt < 256; kt += 16) {
        __syncthreads();   // previous compute finished reading smem
        {
            int kb = lk4 * 4;
            As[kb + 0][lr] = a0.x; As[kb + 1][lr] = a0.y;
            As[kb + 2][lr] = a0.z; As[kb + 3][lr] = a0.w;
            As[kb + 0][lr + 64] = a1.x; As[kb + 1][lr + 64] = a1.y;
            As[kb + 2][lr + 64] = a1.z; As[kb + 3][lr + 64] = a1.w;
            Bs[kb + 0][lr] = w0.x; Bs[kb + 1][lr] = w0.y;
            Bs[kb + 2][lr] = w0.z; Bs[kb + 3][lr] = w0.w;
            Bs[kb + 0][lr + 64] = w1.x; Bs[kb + 1][lr + 64] = w1.y;
            Bs[kb + 2][lr + 64] = w1.z; Bs[kb + 3][lr + 64] = w1.w;
        }
        __syncthreads();

        if (kt < 240) {    // prefetch next tile; latency hides under compute
            a0 = *(const float4*)(aP0 + kt + 16);
            a1 = *(const float4*)(aP1 + kt + 16);
            w0 = *(const float4*)(bP0 + kt + 16);
            w1 = *(const float4*)(bP1 + kt + 16);
        }

#pragma unroll
        for (int k = 0; k < 16; k++) {
            unsigned long long b2[4];
#pragma unroll
            for (int j = 0; j < 4; j++)
                b2[j] = *(const unsigned long long*)&Bs[k][tx * 8 + 2 * j];
            float4 af0 = *(const float4*)&As[k][ty * 8];
            float4 af1 = *(const float4*)&As[k][ty * 8 + 4];
            float a[8] = {af0.x, af0.y, af0.z, af0.w, af1.x, af1.y, af1.z, af1.w};
#pragma unroll
            for (int i = 0; i < 8; i++) {
                unsigned long long a2 = dup2(a[i]);
#pragma unroll
                for (int j = 0; j < 4; j++) ffma2(acc[i][j], a2, b2[j]);
            }
        }
    }

    float bias_r[8];
#pragma unroll
    for (int j = 0; j < 8; j++) bias_r[j] = bl[n0 + tx * 8 + j];
#pragma unroll
    for (int i = 0; i < 8; i++) {
        float o[8];
#pragma unroll
        for (int j = 0; j < 4; j++) {
            float2 v = unpack2(acc[i][j]);
            o[2 * j + 0] = v.x + bias_r[2 * j + 0];
            o[2 * j + 1] = v.y + bias_r[2 * j + 1];
        }
        float* crow = Cout + (size_t)(m0 + ty * 8 + i) * G4 + n0 + tx * 8;
        *(float4*)(crow + 0) = make_float4(o[0], o[1], o[2], o[3]);
        *(float4*)(crow + 4) = make_float4(o[4], o[5], o[6], o[7]);
    }
}

// ============================================================
// Recurrence scan. Grid = 128 CTAs, cluster = 8 CTAs, 256 thr.
// Cluster c owns batches {2c, 2c+1}. CTA rank owns h-indices
// [rank*32, rank*32+32) x 4 gates (128 R rows in registers).
// Per-step sync: DSMEM multicast of new h + mbarrier (count=8)
// with per-rank release-arrive / acquire-parity-wait. No
// cluster barrier (and no CCTL.IVALL L1 flush) in the loop.
// ============================================================
__global__ void __launch_bounds__(256, 1) __cluster_dims__(8, 1, 1)
lstm_scan(const float* __restrict__ Rl,
          const float* __restrict__ h0,
          const float* __restrict__ c0,
          float* __restrict__ xex, int osel)
{
    float* xnext = (osel == 2) ? xex : (osel == 0 ? g_xbuf0 : g_xbuf1);
    const float* gates = g_gates;

    __shared__ __align__(16) float hs[2][2][H];        // parity, batch, hidden
    __shared__ __align__(16) float gxs[2][2][4][32];   // parity, batch, gate, jj
    __shared__ __align__(16) float hnew[2][32];        // staging for broadcast
    __shared__ __align__(8) unsigned long long mbar;

    const int tid = threadIdx.x;
    const int rank = (int)ctarank();
    const int b0 = (blockIdx.x >> 3) * 2;
    const int sub = tid & 7;
    const int jj = tid >> 3;
    const int hidx = rank * 32 + jj;
    const bool owner = (sub == 0);

    // ---- register-resident R slice: 4 gates x 16 column pairs ----
    unsigned long long Rf[4][16];
#pragma unroll
    for (int g = 0; g < 4; g++) {
        const float* base = Rl + (size_t)(g * 256 + hidx) * 256;
#pragma unroll
        for (int k2 = 0; k2 < 16; k2++)
            Rf[g][k2] = *(const unsigned long long*)(base + sub * 2 + 16 * k2);
    }

    // ---- initial h (full 512 floats per CTA) and c (owner regs) ----
    for (int i = tid; i < 2 * H; i += 256) {
        int b = i >> 8, idx = i & 255;
        hs[0][b][idx] = h0[(size_t)(b0 + b) * H + idx];
    }
    float c0r = 0.f, c1r = 0.f;
    if (owner) {
        c0r = c0[(size_t)(b0 + 0) * H + hidx];
        c1r = c0[(size_t)(b0 + 1) * H + hidx];
    }

    // gate-x loader role (one value per step per thread)
    const int gb = tid >> 7;
    const int grem = tid & 127;
    const int gg_ = grem >> 5;
    const int gj = grem & 31;
    const size_t gcol = (size_t)(gg_ * 256 + rank * 32 + gj);
    gxs[0][gb][gg_][gj] = gates[(size_t)(b0 + gb) * G4 + gcol];  // t = 0

    // ---- loop-invariant DSMEM addresses ----
    // broadcast role: warp w -> rank w; each thread one float2
    const int br = tid >> 5;
    const int bidx = tid & 31;
    const int bb = bidx >> 4, bj2 = bidx & 15;
    const uint32_t dst0 = mapa_rank(smem_u32(&hs[1][bb][rank * 32 + bj2 * 2]), br);
    const uint32_t dst1 = mapa_rank(smem_u32(&hs[0][bb][rank * 32 + bj2 * 2]), br);
    // remote mbarrier addresses (tid < 8 arrive at rank=tid)
    const uint32_t lmb = smem_u32((const void*)&mbar);
    uint32_t rmb = 0;
    if (tid < 8) rmb = mapa_rank(lmb, tid);

    if (tid == 0) mbar_init(lmb, 8);
    __syncthreads();
    asm volatile("barrier.cluster.arrive.aligned;" ::: "memory");
    asm volatile("barrier.cluster.wait.aligned;" ::: "memory");

    int p = 0;
    for (int t = 0; t < S; t++) {
        // prefetch next step's gates_x (hides latency under the dot)
        int t1 = (t + 1 < S) ? (t + 1) : (S - 1);
        float gnext = gates[(size_t)(t1 * B + b0 + gb) * G4 + gcol];

        // ---- dot: acc[g][b] over this thread's 32 columns ----
        unsigned long long acc[4][2] = {{0ull, 0ull}, {0ull, 0ull},
                                        {0ull, 0ull}, {0ull, 0ull}};
        const float* hp0 = &hs[p][0][sub * 2];
        const float* hp1 = &hs[p][1][sub * 2];
#pragma unroll
        for (int k2 = 0; k2 < 16; k2++) {
            unsigned long long h0v = *(const unsigned long long*)(hp0 + 16 * k2);
            unsigned long long h1v = *(const unsigned long long*)(hp1 + 16 * k2);
#pragma unroll
            for (int g = 0; g < 4; g++) {
                ffma2(acc[g][0], Rf[g][k2], h0v);
                ffma2(acc[g][1], Rf[g][k2], h1v);
            }
        }

        // ---- reduce over the 8-lane column group ----
        float red[4][2];
#pragma unroll
        for (int g = 0; g < 4; g++)
#pragma unroll
            for (int b = 0; b < 2; b++) {
                float2 v = unpack2(acc[g][b]);
                float s = v.x + v.y;
                s += __shfl_xor_sync(0xffffffffu, s, 1);
                s += __shfl_xor_sync(0xffffffffu, s, 2);
                s += __shfl_xor_sync(0xffffffffu, s, 4);
                red[g][b] = s;
            }

        // stage next step's gates_x (buffer (t+1)&1 is free: its readers
        // finished before the previous step's post-broadcast barrier)
        gxs[(t + 1) & 1][gb][gg_][gj] = gnext;

        // ---- cell epilogue (owner lanes; branch-free activations) ----
        if (owner) {
#pragma unroll
            for (int b = 0; b < 2; b++) {
                float gi = red[0][b] + gxs[t & 1][b][0][jj];
                float gf = red[1][b] + gxs[t & 1][b][1][jj];
                float gG = red[2][b] + gxs[t & 1][b][2][jj];
                float go = red[3][b] + gxs[t & 1][b][3][jj];
                float iv = fsigm(gi);
                float fv = fsigm(gf);
                float gv = ftanh(gG);
                float ov = fsigm(go);
                float cold = b ? c1r : c0r;
                float cnew = fv * cold + iv * gv;
                if (b) c1r = cnew; else c0r = cnew;
                hnew[b][jj] = ov * ftanh(cnew);
            }
        }
        __syncthreads();   // hnew ready for broadcast

        // ---- DSMEM multicast: 64 new h floats -> all 8 ranks ----
        {
            float2 v = ((const float2*)&hnew[bb][0])[bj2];
            uint32_t dst = (p == 0) ? dst0 : dst1;   // writes hs[p^1]
            asm volatile("st.shared::cluster.v2.f32 [%0], {%1, %2};"
                         :: "r"(dst), "f"(v.x), "f"(v.y) : "memory");
        }
        // global write of this CTA's h slice (hnew stable until next epi)
        if (tid < 16) {
            int b = tid >> 3, q = tid & 7;
            float4 v = ((const float4*)&hnew[b][0])[q];
            *(float4*)&xnext[(size_t)(t * B + b0 + b) * H + rank * 32 + q * 4] = v;
        }
        __syncthreads();   // all DSMEM stores issued CTA-wide

        if (tid < 8) mbar_arrive_cluster(rmb);   // release: publishes stores
        mbar_wait(lmb, (uint32_t)(t & 1));       // acquire: peers' h visible
        p ^= 1;
    }

    asm volatile("barrier.cluster.arrive.aligned;" ::: "memory");
    asm volatile("barrier.cluster.wait.aligned;" ::: "memory");
}

// ============================================================
// Host: 4 x (GEMM, SCAN), ping-pong x buffers, all on stream 0.
// ============================================================
extern "C" void kernel_launch(void* const* d_in, const int* in_sizes, int n_in,
                              void* d_out, int out_size)
{
    const float* h_data = (const float*)d_in[0];
    const float* x_data = (const float*)d_in[1];
    const float* c_data = (const float*)d_in[2];
    const float* W      = (const float*)d_in[3];
    const float* R      = (const float*)d_in[4];
    const float* bias   = (const float*)d_in[5];
    float* out = (float*)d_out;

    const dim3 ggrid(8, 256);               // N/128, M/128
    const size_t wstride = (size_t)G4 * H;  // per-layer W/R stride

    lstm_gemm<<<ggrid, 256>>>(x_data, 0, W + 0 * wstride, bias + 0 * G4);
    lstm_scan<<<128, 256>>>(R + 0 * wstride,
                            h_data + 0 * (size_t)LSTRIDE,
                            c_data + 0 * (size_t)LSTRIDE,
                            nullptr, 0);
    lstm_gemm<<<ggrid, 256>>>(nullptr, 1, W + 1 * wstride, bias + 1 * G4);
    lstm_scan<<<128, 256>>>(R + 1 * wstride,
                            h_data + 1 * (size_t)LSTRIDE,
                            c_data + 1 * (size_t)LSTRIDE,
                            nullptr, 1);
    lstm_gemm<<<ggrid, 256>>>(nullptr, 2, W + 2 * wstride, bias + 2 * G4);
    lstm_scan<<<128, 256>>>(R + 2 * wstride,
                            h_data + 2 * (size_t)LSTRIDE,
                            c_data + 2 * (size_t)LSTRIDE,
                            nullptr, 0);
    lstm_gemm<<<ggrid, 256>>>(nullptr, 1, W + 3 * wstride, bias + 3 * G4);
    lstm_scan<<<128, 256>>>(R + 3 * wstride,
                            h_data + 3 * (size_t)LSTRIDE,
                            c_data + 3 * (size_t)LSTRIDE,
                            out, 2);
}

// round 12
// speedup vs baseline: 2.1158x; 1.3189x over previous
#include <cuda_runtime.h>
#include <cstdint>

#define H 256
#define B 32
#define S 1024
#define NL 4
#define NE (H * B)              // 8192
#define G4 (4 * H)              // 1024
#define MROWS (S * B)           // 32768
#define LSTRIDE ((S + 1) * NE)  // per-layer h0/c0 slab stride

// -------- static scratch (allowed: __device__ globals) --------
__device__ float g_gates[(size_t)MROWS * G4];   // 128 MB: [t*B+b][4H]
__device__ float g_xbuf0[(size_t)MROWS * H];    // 32 MB:  [t*B+b][H]
__device__ float g_xbuf1[(size_t)MROWS * H];    // 32 MB

// -------- helpers --------
__device__ __forceinline__ void ffma2(unsigned long long& d,
                                      unsigned long long a,
                                      unsigned long long b) {
    asm("fma.rn.f32x2 %0, %1, %2, %0;" : "+l"(d) : "l"(a), "l"(b));
}
__device__ __forceinline__ unsigned long long dup2(float a) {
    unsigned long long r;
    asm("mov.b64 %0, {%1, %1};" : "=l"(r) : "f"(a));
    return r;
}
__device__ __forceinline__ float2 unpack2(unsigned long long v) {
    float2 f;
    asm("mov.b64 {%0, %1}, %2;" : "=f"(f.x), "=f"(f.y) : "l"(v));
    return f;
}
__device__ __forceinline__ uint32_t smem_u32(const void* p) {
    return (uint32_t)__cvta_generic_to_shared(p);
}
__device__ __forceinline__ uint32_t ctarank() {
    uint32_t r;
    asm("mov.u32 %0, %%cluster_ctarank;" : "=r"(r));
    return r;
}
__device__ __forceinline__ uint32_t mapa_rank(uint32_t laddr, int r) {
    uint32_t ra;
    asm("mapa.shared::cluster.u32 %0, %1, %2;" : "=r"(ra) : "r"(laddr), "r"(r));
    return ra;
}
// fast, branch-free activations (rel err ~1e-6; saturate correctly)
__device__ __forceinline__ float fsigm(float x) {
    return __fdividef(1.0f, 1.0f + __expf(-x));
}
__device__ __forceinline__ float ftanh(float x) {
    return __fdividef(2.0f, 1.0f + __expf(-2.0f * x)) - 1.0f;
}
__device__ __forceinline__ void mbar_init(uint32_t a, int cnt) {
    asm volatile("mbarrier.init.shared.b64 [%0], %1;" :: "r"(a), "r"(cnt) : "memory");
}
__device__ __forceinline__ void mbar_expect(uint32_t a, uint32_t bytes) {
    asm volatile("mbarrier.arrive.expect_tx.shared.b64 _, [%0], %1;"
                 :: "r"(a), "r"(bytes) : "memory");
}
// st.async: data + completion bytes delivered to the DESTINATION CTA's
// mbarrier. No fence, no drain — the tx count IS the visibility guarantee.
__device__ __forceinline__ void st_async_b64(uint32_t dst, unsigned long long v,
                                             uint32_t rbar) {
    asm volatile(
        "st.async.weak.shared::cluster.mbarrier::complete_tx::bytes.b64 [%0], %1, [%2];"
        :: "r"(dst), "l"(v), "r"(rbar) : "memory");
}
__device__ __forceinline__ void mbar_wait(uint32_t a, uint32_t parity) {
    uint32_t done;
    asm volatile(
        "{\n\t.reg .pred p;\n\t"
        "mbarrier.try_wait.parity.acquire.cta.shared::cta.b64 p, [%1], %2;\n\t"
        "selp.b32 %0, 1, 0, p;\n\t}"
        : "=r"(done) : "r"(a), "r"(parity) : "memory");
    if (!done) {
        asm volatile(
            "{\n\t.reg .pred P1;\n\t"
            "W_%=:\n\t"
            "mbarrier.try_wait.parity.acquire.cta.shared::cta.b64 P1, [%0], %1, 0x989680;\n\t"
            "@P1 bra.uni D_%=;\n\t"
            "bra.uni W_%=;\n\t"
            "D_%=:\n\t}"
            :: "r"(a), "r"(parity) : "memory");
    }
}

// ============================================================
// GEMM: C[M=32768, N=1024] = A[M,256] @ W^T + bias
// BM=128, BN=128, BK=16, 256 threads, 8x8 microtile, FFMA2.
// ============================================================
__global__ void __launch_bounds__(256, 2)
lstm_gemm(const float* __restrict__ Aex, int asel,
          const float* __restrict__ Wl,
          const float* __restrict__ bl)
{
    const float* A = (asel == 0) ? Aex : (asel == 1 ? g_xbuf0 : g_xbuf1);
    float* Cout = g_gates;

    __shared__ __align__(16) float As[16][128];
    __shared__ __align__(16) float Bs[16][128];

    const int tid = threadIdx.x;
    const int n0 = blockIdx.x * 128;
    const int m0 = blockIdx.y * 128;
    const int tx = tid & 15, ty = tid >> 4;

    const int lr = tid >> 2;        // 0..63
    const int lk4 = tid & 3;        // 0..3

    unsigned long long acc[8][4];
#pragma unroll
    for (int i = 0; i < 8; i++)
#pragma unroll
        for (int j = 0; j < 4; j++) acc[i][j] = 0ull;

    const float* aP0 = A  + (size_t)(m0 + lr)      * 256 + lk4 * 4;
    const float* aP1 = A  + (size_t)(m0 + lr + 64) * 256 + lk4 * 4;
    const float* bP0 = Wl + (size_t)(n0 + lr)      * 256 + lk4 * 4;
    const float* bP1 = Wl + (size_t)(n0 + lr + 64) * 256 + lk4 * 4;

    float4 a0 = *(const float4*)(aP0);
    float4 a1 = *(const float4*)(aP1);
    float4 w0 = *(const float4*)(bP0);
    float4 w1 = *(const float4*)(bP1);

    for (int kt = 0; kt < 256; kt += 16) {
        __syncthreads();
        {
            int kb = lk4 * 4;
            As[kb + 0][lr] = a0.x; As[kb + 1][lr] = a0.y;
            As[kb + 2][lr] = a0.z; As[kb + 3][lr] = a0.w;
            As[kb + 0][lr + 64] = a1.x; As[kb + 1][lr + 64] = a1.y;
            As[kb + 2][lr + 64] = a1.z; As[kb + 3][lr + 64] = a1.w;
            Bs[kb + 0][lr] = w0.x; Bs[kb + 1][lr] = w0.y;
            Bs[kb + 2][lr] = w0.z; Bs[kb + 3][lr] = w0.w;
            Bs[kb + 0][lr + 64] = w1.x; Bs[kb + 1][lr + 64] = w1.y;
            Bs[kb + 2][lr + 64] = w1.z; Bs[kb + 3][lr + 64] = w1.w;
        }
        __syncthreads();

        if (kt < 240) {
            a0 = *(const float4*)(aP0 + kt + 16);
            a1 = *(const float4*)(aP1 + kt + 16);
            w0 = *(const float4*)(bP0 + kt + 16);
            w1 = *(const float4*)(bP1 + kt + 16);
        }

#pragma unroll
        for (int k = 0; k < 16; k++) {
            unsigned long long b2[4];
#pragma unroll
            for (int j = 0; j < 4; j++)
                b2[j] = *(const unsigned long long*)&Bs[k][tx * 8 + 2 * j];
            float4 af0 = *(const float4*)&As[k][ty * 8];
            float4 af1 = *(const float4*)&As[k][ty * 8 + 4];
            float a[8] = {af0.x, af0.y, af0.z, af0.w, af1.x, af1.y, af1.z, af1.w};
#pragma unroll
            for (int i = 0; i < 8; i++) {
                unsigned long long a2 = dup2(a[i]);
#pragma unroll
                for (int j = 0; j < 4; j++) ffma2(acc[i][j], a2, b2[j]);
            }
        }
    }

    float bias_r[8];
#pragma unroll
    for (int j = 0; j < 8; j++) bias_r[j] = bl[n0 + tx * 8 + j];
#pragma unroll
    for (int i = 0; i < 8; i++) {
        float o[8];
#pragma unroll
        for (int j = 0; j < 4; j++) {
            float2 v = unpack2(acc[i][j]);
            o[2 * j + 0] = v.x + bias_r[2 * j + 0];
            o[2 * j + 1] = v.y + bias_r[2 * j + 1];
        }
        float* crow = Cout + (size_t)(m0 + ty * 8 + i) * G4 + n0 + tx * 8;
        *(float4*)(crow + 0) = make_float4(o[0], o[1], o[2], o[3]);
        *(float4*)(crow + 4) = make_float4(o[4], o[5], o[6], o[7]);
    }
}

// ============================================================
// Recurrence scan. 16 clusters x 8 CTAs, 256 thr. Cluster owns
// batches {2c,2c+1}; CTA rank owns 32 h-indices x 4 gates (R in
// registers). Per-step sync: st.async h-broadcast completing the
// destination's transaction mbarrier (2048 B = 8 ranks x 256 B).
// Two barriers (even/odd step) so expect_tx for step t+1 posts
// BEFORE waiting on step t -> no expect/complete race, and zero
// fences anywhere in the loop.
// ============================================================
__global__ void __launch_bounds__(256, 1) __cluster_dims__(8, 1, 1)
lstm_scan(const float* __restrict__ Rl,
          const float* __restrict__ h0,
          const float* __restrict__ c0,
          float* __restrict__ xex, int osel)
{
    float* xnext = (osel == 2) ? xex : (osel == 0 ? g_xbuf0 : g_xbuf1);
    const float* gates = g_gates;

    __shared__ __align__(16) float hs[2][2][H];        // buffer, batch, hidden
    __shared__ __align__(16) float gxs[2][2][4][32];   // parity, batch, gate, jj
    __shared__ __align__(16) float hnew[2][32];
    __shared__ __align__(8) unsigned long long mbars[2];  // even/odd step

    const int tid = threadIdx.x;
    const int rank = (int)ctarank();
    const int b0 = (blockIdx.x >> 3) * 2;
    const int sub = tid & 7;
    const int jj = tid >> 3;
    const int hidx = rank * 32 + jj;

    // ---- register-resident R slice: 4 gates x 16 column pairs ----
    unsigned long long Rf[4][16];
#pragma unroll
    for (int g = 0; g < 4; g++) {
        const float* base = Rl + (size_t)(g * 256 + hidx) * 256;
#pragma unroll
        for (int k2 = 0; k2 < 16; k2++)
            Rf[g][k2] = *(const unsigned long long*)(base + sub * 2 + 16 * k2);
    }

    // ---- initial h and c ----
    for (int i = tid; i < 2 * H; i += 256) {
        int b = i >> 8, idx = i & 255;
        hs[0][b][idx] = h0[(size_t)(b0 + b) * H + idx];
    }
    // epilogue split: lane sub==0 owns batch 0, sub==1 owns batch 1
    const int myb = sub;                 // meaningful for sub < 2
    const bool is_owner = (sub < 2);
    float creg = 0.f;
    if (is_owner) creg = c0[(size_t)(b0 + myb) * H + hidx];

    // gate-x loader role (one value per step per thread)
    const int gb = tid >> 7;
    const int grem = tid & 127;
    const int gg_ = grem >> 5;
    const int gj = grem & 31;
    const size_t gcol = (size_t)(gg_ * 256 + rank * 32 + gj);
    gxs[0][gb][gg_][gj] = gates[(size_t)(b0 + gb) * G4 + gcol];  // t = 0

    // ---- loop-invariant DSMEM addresses ----
    // broadcast role: warp w -> rank w; each thread one float2 (8 B)
    const int br = tid >> 5;
    const int bidx = tid & 31;
    const int bb = bidx >> 4, bj2 = bidx & 15;
    const uint32_t dstA = mapa_rank(smem_u32(&hs[1][bb][rank * 32 + bj2 * 2]), br);
    const uint32_t dstB = mapa_rank(smem_u32(&hs[0][bb][rank * 32 + bj2 * 2]), br);
    const uint32_t lmb0 = smem_u32((const void*)&mbars[0]);
    const uint32_t lmb1 = smem_u32((const void*)&mbars[1]);
    const uint32_t rmb0 = mapa_rank(lmb0, br);
    const uint32_t rmb1 = mapa_rank(lmb1, br);

    if (tid == 0) {
        mbar_init(lmb0, 1);
        mbar_init(lmb1, 1);
        mbar_expect(lmb0, 2048);   // expect for t = 0
    }
    __syncthreads();
    asm volatile("barrier.cluster.arrive.aligned;" ::: "memory");
    asm volatile("barrier.cluster.wait.aligned;" ::: "memory");

    int p = 0;
    for (int t = 0; t < S; t++) {
        // prefetch next step's gates_x (hides DRAM latency under the dot)
        int t1 = (t + 1 < S) ? (t + 1) : (S - 1);
        float gnext = gates[(size_t)(t1 * B + b0 + gb) * G4 + gcol];

        // ---- dot: acc[g][b] over this thread's 32 columns ----
        unsigned long long acc[4][2] = {{0ull, 0ull}, {0ull, 0ull},
                                        {0ull, 0ull}, {0ull, 0ull}};
        const float* hp0 = &hs[p][0][sub * 2];
        const float* hp1 = &hs[p][1][sub * 2];
#pragma unroll
        for (int k2 = 0; k2 < 16; k2++) {
            unsigned long long h0v = *(const unsigned long long*)(hp0 + 16 * k2);
            unsigned long long h1v = *(const unsigned long long*)(hp1 + 16 * k2);
#pragma unroll
            for (int g = 0; g < 4; g++) {
                ffma2(acc[g][0], Rf[g][k2], h0v);
                ffma2(acc[g][1], Rf[g][k2], h1v);
            }
        }

        // ---- reduce over the 8-lane column group ----
        float red[4][2];
#pragma unroll
        for (int g = 0; g < 4; g++)
#pragma unroll
            for (int b = 0; b < 2; b++) {
                float2 v = unpack2(acc[g][b]);
                float s = v.x + v.y;
                s += __shfl_xor_sync(0xffffffffu, s, 1);
                s += __shfl_xor_sync(0xffffffffu, s, 2);
                s += __shfl_xor_sync(0xffffffffu, s, 4);
                red[g][b] = s;
            }

        // stage next step's gates_x
        gxs[(t + 1) & 1][gb][gg_][gj] = gnext;

        // ---- cell epilogue (two lanes per jj: sub==b) ----
        if (is_owner) {
            float gi = red[0][myb] + gxs[t & 1][myb][0][jj];
            float gf = red[1][myb] + gxs[t & 1][myb][1][jj];
            float gG = red[2][myb] + gxs[t & 1][myb][2][jj];
            float go = red[3][myb] + gxs[t & 1][myb][3][jj];
            float iv = fsigm(gi);
            float fv = fsigm(gf);
            float gv = ftanh(gG);
            float ov = fsigm(go);
            float cnew = fv * creg + iv * gv;
            creg = cnew;
            hnew[myb][jj] = ov * ftanh(cnew);
        }
        __syncthreads();   // hnew ready for broadcast

        // ---- st.async multicast: 64 new h floats -> all 8 ranks ----
        {
            unsigned long long v =
                *(const unsigned long long*)&hnew[bb][bj2 * 2];
            uint32_t dst = (p == 0) ? dstA : dstB;      // writes hs[p^1]
            uint32_t rb  = (t & 1) ? rmb1 : rmb0;       // step-t barrier
            st_async_b64(dst, v, rb);
        }
        // post expect for step t+1 NOW (guaranteed earlier than any peer's
        // t+1 bytes: those need our step-t bytes + a full peer step first)
        if (tid == 0) mbar_expect((t & 1) ? lmb0 : lmb1, 2048);

        // global write of this CTA's h slice (off all sync paths)
        if (tid < 16) {
            int b = tid >> 3, q = tid & 7;
            float4 v = ((const float4*)&hnew[b][0])[q];
            *(float4*)&xnext[(size_t)(t * B + b0 + b) * H + rank * 32 + q * 4] = v;
        }

        // wait for all 2048 B of step t to land in hs[p^1]
        mbar_wait((t & 1) ? lmb1 : lmb0, (uint32_t)((t >> 1) & 1));
        p ^= 1;
    }

    // keep smem alive until every peer's last st.async has landed
    asm volatile("barrier.cluster.arrive.aligned;" ::: "memory");
    asm volatile("barrier.cluster.wait.aligned;" ::: "memory");
}

// ============================================================
// Host: 4 x (GEMM, SCAN), ping-pong x buffers, all on stream 0.
// ============================================================
extern "C" void kernel_launch(void* const* d_in, const int* in_sizes, int n_in,
                              void* d_out, int out_size)
{
    const float* h_data = (const float*)d_in[0];
    const float* x_data = (const float*)d_in[1];
    const float* c_data = (const float*)d_in[2];
    const float* W      = (const float*)d_in[3];
    const float* R      = (const float*)d_in[4];
    const float* bias   = (const float*)d_in[5];
    float* out = (float*)d_out;

    const dim3 ggrid(8, 256);               // N/128, M/128
    const size_t wstride = (size_t)G4 * H;

    lstm_gemm<<<ggrid, 256>>>(x_data, 0, W + 0 * wstride, bias + 0 * G4);
    lstm_scan<<<128, 256>>>(R + 0 * wstride,
                            h_data + 0 * (size_t)LSTRIDE,
                            c_data + 0 * (size_t)LSTRIDE,
                            nullptr, 0);
    lstm_gemm<<<ggrid, 256>>>(nullptr, 1, W + 1 * wstride, bias + 1 * G4);
    lstm_scan<<<128, 256>>>(R + 1 * wstride,
                            h_data + 1 * (size_t)LSTRIDE,
                            c_data + 1 * (size_t)LSTRIDE,
                            nullptr, 1);
    lstm_gemm<<<ggrid, 256>>>(nullptr, 2, W + 2 * wstride, bias + 2 * G4);
    lstm_scan<<<128, 256>>>(R + 2 * wstride,
                            h_data + 2 * (size_t)LSTRIDE,
                            c_data + 2 * (size_t)LSTRIDE,
                            nullptr, 0);
    lstm_gemm<<<ggrid, 256>>>(nullptr, 1, W + 3 * wstride, bias + 3 * G4);
    lstm_scan<<<128, 256>>>(R + 3 * wstride,
                            h_data + 3 * (size_t)LSTRIDE,
                            c_data + 3 * (size_t)LSTRIDE,
                            out, 2);
}